// round 1
// baseline (speedup 1.0000x reference)
#include <cuda_runtime.h>
#include <math.h>

#define B_   2
#define S_   2048
#define D_   1024
#define H_   16
#define DH_  64
#define M_   (B_*S_)          // 4096 tokens
#define BH_  (B_*H_)          // 32
#define KK_  512              // top-k
#define MCH_ 16               // mean chunks

// ---------------- scratch (static device memory; no allocations) ----------------
__device__ float g_q[M_*D_];
__device__ float g_k[M_*D_];
__device__ float g_v[M_*D_];
__device__ float g_gatep[M_*D_];
__device__ float g_qn[M_*D_];     // [BH][S][DH]
__device__ float g_kn[M_*D_];     // [BH][S][DH]
__device__ float g_vh[M_*D_];     // [BH][S][DH]
__device__ float g_obsd[M_*D_];   // attention output back in [B,S,D]
__device__ float g_out2[M_*D_];   // after Wo
__device__ float g_scores[(size_t)BH_*S_*S_];   // 512MB: scores, then attn weights in-place
__device__ float g_xpart[MCH_*B_*D_];
__device__ float g_xmean[B_*D_];
__device__ float g_temp[B_];

// ---------------- mean over sequence (2-stage, deterministic) ----------------
__global__ __launch_bounds__(256) void mean_stage1(const float* __restrict__ x){
    int b  = blockIdx.x / MCH_;
    int ch = blockIdx.x % MCH_;
    int s0 = ch * (S_/MCH_);
    int tid = threadIdx.x;
    float acc[4] = {0.f,0.f,0.f,0.f};
    for (int s = s0; s < s0 + S_/MCH_; ++s){
        const float* xp = x + ((size_t)(b*S_+s))*D_;
        #pragma unroll
        for (int j = 0; j < 4; ++j) acc[j] += xp[tid + j*256];
    }
    #pragma unroll
    for (int j = 0; j < 4; ++j) g_xpart[((size_t)ch*B_ + b)*D_ + tid + j*256] = acc[j];
}

__global__ __launch_bounds__(256) void mean_stage2(){
    int idx = blockIdx.x*256 + threadIdx.x;   // B*D = 2048 total
    int b = idx / D_, d = idx % D_;
    float s = 0.f;
    #pragma unroll
    for (int ch = 0; ch < MCH_; ++ch) s += g_xpart[((size_t)ch*B_ + b)*D_ + d];
    g_xmean[idx] = s * (1.0f/S_);
}

// ---------------- adaptive temperature ----------------
__global__ __launch_bounds__(256) void temp_kernel(const float* __restrict__ Wt,
                                                   const float* __restrict__ bt){
    __shared__ float red[256];
    int b = blockIdx.x, tid = threadIdx.x;
    float s = 0.f;
    for (int d = tid; d < D_; d += 256) s += g_xmean[b*D_ + d] * Wt[d];
    red[tid] = s; __syncthreads();
    for (int o = 128; o; o >>= 1){ if (tid < o) red[tid] += red[tid+o]; __syncthreads(); }
    if (tid == 0) g_temp[b] = 1.0f/(1.0f + expf(-(red[0] + bt[0]))) + 0.5f;
}

// ---------------- generic SGEMM C = A@W + bias ----------------
// BM=BN=128, BK=8, 256 threads, 8x8 per thread
__global__ __launch_bounds__(256) void sgemm_bias(const float* __restrict__ A,
                                                  const float* __restrict__ Bw,
                                                  const float* __restrict__ bias,
                                                  float* __restrict__ C,
                                                  int M, int N, int K){
    __shared__ float As[8][132];
    __shared__ float Bs[8][128];
    const int tid = threadIdx.x;
    const int m0 = blockIdx.y*128, n0 = blockIdx.x*128;
    const int tr = tid >> 4, tc = tid & 15;
    float acc[8][8];
    #pragma unroll
    for (int i = 0; i < 8; ++i)
        #pragma unroll
        for (int j = 0; j < 8; ++j) acc[i][j] = 0.f;

    const int aRow = tid >> 1;          // 0..127
    const int aC4  = (tid & 1) << 2;    // 0 or 4
    const int bRow = tid >> 5;          // 0..7
    const int bC4  = (tid & 31) << 2;   // 0..124

    for (int k0 = 0; k0 < K; k0 += 8){
        float4 av = *reinterpret_cast<const float4*>(A + (size_t)(m0+aRow)*K + k0 + aC4);
        As[aC4+0][aRow] = av.x; As[aC4+1][aRow] = av.y;
        As[aC4+2][aRow] = av.z; As[aC4+3][aRow] = av.w;
        *reinterpret_cast<float4*>(&Bs[bRow][bC4]) =
            *reinterpret_cast<const float4*>(Bw + (size_t)(k0+bRow)*N + n0 + bC4);
        __syncthreads();
        #pragma unroll
        for (int k = 0; k < 8; ++k){
            float a[8], b[8];
            *(float4*)&a[0] = *(float4*)&As[k][tr*8];
            *(float4*)&a[4] = *(float4*)&As[k][tr*8+4];
            *(float4*)&b[0] = *(float4*)&Bs[k][tc*8];
            *(float4*)&b[4] = *(float4*)&Bs[k][tc*8+4];
            #pragma unroll
            for (int i = 0; i < 8; ++i)
                #pragma unroll
                for (int j = 0; j < 8; ++j) acc[i][j] += a[i]*b[j];
        }
        __syncthreads();
    }
    #pragma unroll
    for (int i = 0; i < 8; ++i){
        int r = m0 + tr*8 + i;
        #pragma unroll
        for (int j = 0; j < 8; j += 4){
            int c = n0 + tc*8 + j;
            float4 o;
            o.x = acc[i][j]   + bias[c];
            o.y = acc[i][j+1] + bias[c+1];
            o.z = acc[i][j+2] + bias[c+2];
            o.w = acc[i][j+3] + bias[c+3];
            *reinterpret_cast<float4*>(C + (size_t)r*N + c) = o;
        }
    }
}

// ---------------- head split + L2 normalize (q,k) + v relayout ----------------
__global__ __launch_bounds__(256) void norm_split(){
    int gw   = (blockIdx.x*256 + threadIdx.x) >> 5;   // one warp per (bh,s)
    int lane = threadIdx.x & 31;
    int s  = gw & (S_-1);
    int bh = gw >> 11;            // S_=2048
    int h  = bh & (H_-1), b = bh >> 4;
    size_t src = ((size_t)(b*S_+s))*D_ + h*DH_;
    size_t dst = (size_t)gw * DH_;

    float2 qv = reinterpret_cast<const float2*>(g_q + src)[lane];
    float ss = qv.x*qv.x + qv.y*qv.y;
    #pragma unroll
    for (int o = 16; o; o >>= 1) ss += __shfl_xor_sync(0xFFFFFFFFu, ss, o);
    float inv = 1.0f / fmaxf(sqrtf(ss), 1e-12f);
    reinterpret_cast<float2*>(g_qn + dst)[lane] = make_float2(qv.x*inv, qv.y*inv);

    float2 kv = reinterpret_cast<const float2*>(g_k + src)[lane];
    ss = kv.x*kv.x + kv.y*kv.y;
    #pragma unroll
    for (int o = 16; o; o >>= 1) ss += __shfl_xor_sync(0xFFFFFFFFu, ss, o);
    inv = 1.0f / fmaxf(sqrtf(ss), 1e-12f);
    reinterpret_cast<float2*>(g_kn + dst)[lane] = make_float2(kv.x*inv, kv.y*inv);

    reinterpret_cast<float2*>(g_vh + dst)[lane] =
        reinterpret_cast<const float2*>(g_v + src)[lane];
}

// ---------------- scores[bh] = Qn @ Kn^T / temp[b] ----------------
__global__ __launch_bounds__(256) void scores_kernel(){
    const int bh = blockIdx.z;
    const int m0 = blockIdx.y*128;
    const int n0 = blockIdx.x*128;
    const float* Q  = g_qn + (size_t)bh*S_*DH_;
    const float* Kp = g_kn + (size_t)bh*S_*DH_;
    __shared__ float Qs[32][132];
    __shared__ float Ks[32][132];
    const int tid = threadIdx.x;
    const int tr = tid >> 4, tc = tid & 15;
    float acc[8][8];
    #pragma unroll
    for (int i = 0; i < 8; ++i)
        #pragma unroll
        for (int j = 0; j < 8; ++j) acc[i][j] = 0.f;

    for (int k0 = 0; k0 < DH_; k0 += 32){
        #pragma unroll
        for (int q = 0; q < 4; ++q){
            int pos = tid + q*256;
            int row = pos >> 3;
            int c4  = (pos & 7) << 2;
            float4 t = *reinterpret_cast<const float4*>(Q + (size_t)(m0+row)*DH_ + k0 + c4);
            Qs[c4+0][row]=t.x; Qs[c4+1][row]=t.y; Qs[c4+2][row]=t.z; Qs[c4+3][row]=t.w;
            float4 u = *reinterpret_cast<const float4*>(Kp + (size_t)(n0+row)*DH_ + k0 + c4);
            Ks[c4+0][row]=u.x; Ks[c4+1][row]=u.y; Ks[c4+2][row]=u.z; Ks[c4+3][row]=u.w;
        }
        __syncthreads();
        #pragma unroll
        for (int k = 0; k < 32; ++k){
            float a[8], b[8];
            *(float4*)&a[0] = *(float4*)&Qs[k][tr*8];
            *(float4*)&a[4] = *(float4*)&Qs[k][tr*8+4];
            *(float4*)&b[0] = *(float4*)&Ks[k][tc*8];
            *(float4*)&b[4] = *(float4*)&Ks[k][tc*8+4];
            #pragma unroll
            for (int i = 0; i < 8; ++i)
                #pragma unroll
                for (int j = 0; j < 8; ++j) acc[i][j] += a[i]*b[j];
        }
        __syncthreads();
    }
    const int b_idx = bh >> 4;
    const float scale = 1.0f / g_temp[b_idx];
    float* outp = g_scores + ((size_t)bh*S_ + m0)*S_ + n0;
    #pragma unroll
    for (int i = 0; i < 8; ++i){
        int r = tr*8 + i;
        #pragma unroll
        for (int j = 0; j < 8; j += 4){
            float4 o = make_float4(acc[i][j]*scale, acc[i][j+1]*scale,
                                   acc[i][j+2]*scale, acc[i][j+3]*scale);
            *reinterpret_cast<float4*>(outp + (size_t)r*S_ + tc*8 + j) = o;
        }
    }
}

// ---------------- exact top-512 radix-select + softmax, in place ----------------
__global__ __launch_bounds__(256) void topk_softmax(){
    const int row = blockIdx.x;
    float* sp = g_scores + (size_t)row * S_;
    __shared__ unsigned hist[256];
    __shared__ unsigned suf[256];
    __shared__ float fred[256];
    __shared__ unsigned s_bin, s_above;
    const int tid = threadIdx.x;

    float v[8]; unsigned key[8];
    #pragma unroll
    for (int i = 0; i < 8; ++i){
        v[i] = sp[i*256 + tid];
        unsigned u = __float_as_uint(v[i]);
        key[i] = u ^ (((unsigned)((int)u >> 31)) | 0x80000000u);  // monotone map
    }

    unsigned prefix = 0; unsigned remaining = KK_;
    for (int shift = 24; shift >= 0; shift -= 8){
        hist[tid] = 0; __syncthreads();
        unsigned pmask = (shift == 24) ? 0u : (0xFFFFFFFFu << (shift+8));
        #pragma unroll
        for (int i = 0; i < 8; ++i)
            if ((key[i] & pmask) == prefix) atomicAdd(&hist[(key[i] >> shift) & 255], 1u);
        __syncthreads();
        unsigned mine = hist[tid];
        suf[tid] = mine; __syncthreads();
        #pragma unroll
        for (int o = 1; o < 256; o <<= 1){
            unsigned add = (tid + o < 256) ? suf[tid+o] : 0u;
            __syncthreads();
            suf[tid] += add;
            __syncthreads();
        }
        unsigned mysuf = suf[tid];
        unsigned nxt = (tid < 255) ? suf[tid+1] : 0u;
        if (mysuf >= remaining && nxt < remaining){ s_bin = (unsigned)tid; s_above = nxt; }
        __syncthreads();
        remaining -= s_above;
        prefix |= (s_bin << shift);
        __syncthreads();
    }
    const unsigned T = prefix;   // key of 512th-largest

    float mx = -3.402823466e38f;
    #pragma unroll
    for (int i = 0; i < 8; ++i) mx = fmaxf(mx, v[i]);
    fred[tid] = mx; __syncthreads();
    for (int o = 128; o; o >>= 1){ if (tid < o) fred[tid] = fmaxf(fred[tid], fred[tid+o]); __syncthreads(); }
    mx = fred[0]; __syncthreads();

    float e[8]; float lsum = 0.f;
    #pragma unroll
    for (int i = 0; i < 8; ++i){
        e[i] = (key[i] >= T) ? expf(v[i] - mx) : 0.0f;
        lsum += e[i];
    }
    fred[tid] = lsum; __syncthreads();
    for (int o = 128; o; o >>= 1){ if (tid < o) fred[tid] += fred[tid+o]; __syncthreads(); }
    const float inv = 1.0f / fred[0];
    #pragma unroll
    for (int i = 0; i < 8; ++i) sp[i*256 + tid] = e[i]*inv;
}

// ---------------- O[b,s,h*64+d] = attn[bh] @ V[bh] ----------------
__global__ __launch_bounds__(256) void av_kernel(){
    const int bh = blockIdx.z;
    const int m0 = blockIdx.y*128;
    const float* Wm = g_scores + (size_t)bh*S_*S_;
    const float* Vp = g_vh     + (size_t)bh*S_*DH_;
    __shared__ float Ws[32][132];
    __shared__ float Vs[32][64];
    const int tid = threadIdx.x;
    const int tr = tid >> 4, tc = tid & 15;
    float acc[8][4];
    #pragma unroll
    for (int i = 0; i < 8; ++i)
        #pragma unroll
        for (int j = 0; j < 4; ++j) acc[i][j] = 0.f;

    for (int k0 = 0; k0 < S_; k0 += 32){
        #pragma unroll
        for (int q = 0; q < 4; ++q){
            int pos = tid + q*256;
            int row = pos >> 3;
            int c4  = (pos & 7) << 2;
            float4 t = *reinterpret_cast<const float4*>(Wm + (size_t)(m0+row)*S_ + k0 + c4);
            Ws[c4+0][row]=t.x; Ws[c4+1][row]=t.y; Ws[c4+2][row]=t.z; Ws[c4+3][row]=t.w;
        }
        #pragma unroll
        for (int q = 0; q < 2; ++q){
            int pos = tid + q*256;
            int row = pos >> 4;
            int c4  = (pos & 15) << 2;
            *reinterpret_cast<float4*>(&Vs[row][c4]) =
                *reinterpret_cast<const float4*>(Vp + (size_t)(k0+row)*DH_ + c4);
        }
        __syncthreads();
        #pragma unroll
        for (int k = 0; k < 32; ++k){
            float a[8], b[4];
            *(float4*)&a[0] = *(float4*)&Ws[k][tr*8];
            *(float4*)&a[4] = *(float4*)&Ws[k][tr*8+4];
            *(float4*)&b[0] = *(float4*)&Vs[k][tc*4];
            #pragma unroll
            for (int i = 0; i < 8; ++i)
                #pragma unroll
                for (int j = 0; j < 4; ++j) acc[i][j] += a[i]*b[j];
        }
        __syncthreads();
    }
    const int b_idx = bh >> 4, h = bh & (H_-1);
    #pragma unroll
    for (int i = 0; i < 8; ++i){
        int s_idx = m0 + tr*8 + i;
        float4 o = make_float4(acc[i][0], acc[i][1], acc[i][2], acc[i][3]);
        *reinterpret_cast<float4*>(g_obsd + ((size_t)(b_idx*S_ + s_idx))*D_ + h*DH_ + tc*4) = o;
    }
}

// ---------------- highway gating ----------------
__global__ __launch_bounds__(256) void finalize_kernel(const float* __restrict__ x,
                                                       float* __restrict__ out){
    int idx = blockIdx.x*256 + threadIdx.x;    // over M*D/4 float4s
    float4 xp = reinterpret_cast<const float4*>(x)[idx];
    float4 gp = reinterpret_cast<const float4*>(g_gatep)[idx];
    float4 op = reinterpret_cast<const float4*>(g_out2)[idx];
    float4 r;
    float g;
    g = 1.0f/(1.0f+expf(-gp.x)); r.x = g*op.x + (1.0f-g)*xp.x;
    g = 1.0f/(1.0f+expf(-gp.y)); r.y = g*op.y + (1.0f-g)*xp.y;
    g = 1.0f/(1.0f+expf(-gp.z)); r.z = g*op.z + (1.0f-g)*xp.z;
    g = 1.0f/(1.0f+expf(-gp.w)); r.w = g*op.w + (1.0f-g)*xp.w;
    reinterpret_cast<float4*>(out)[idx] = r;
}

// ---------------- launch ----------------
extern "C" void kernel_launch(void* const* d_in, const int* in_sizes, int n_in,
                              void* d_out, int out_size){
    (void)in_sizes; (void)n_in; (void)out_size;
    const float* x  = (const float*)d_in[0];
    const float* Wq = (const float*)d_in[1];  const float* bq = (const float*)d_in[2];
    const float* Wk = (const float*)d_in[3];  const float* bk = (const float*)d_in[4];
    const float* Wv = (const float*)d_in[5];  const float* bv = (const float*)d_in[6];
    const float* Wo = (const float*)d_in[7];  const float* bo = (const float*)d_in[8];
    const float* Wt = (const float*)d_in[9];  const float* bt = (const float*)d_in[10];
    const float* Wg = (const float*)d_in[11]; const float* bg = (const float*)d_in[12];
    float* out = (float*)d_out;

    float *p_q, *p_k, *p_v, *p_g, *p_obsd, *p_out2;
    cudaGetSymbolAddress((void**)&p_q,    g_q);
    cudaGetSymbolAddress((void**)&p_k,    g_k);
    cudaGetSymbolAddress((void**)&p_v,    g_v);
    cudaGetSymbolAddress((void**)&p_g,    g_gatep);
    cudaGetSymbolAddress((void**)&p_obsd, g_obsd);
    cudaGetSymbolAddress((void**)&p_out2, g_out2);

    // temperature path
    mean_stage1<<<B_*MCH_, 256>>>(x);
    mean_stage2<<<(B_*D_)/256, 256>>>();
    temp_kernel<<<B_, 256>>>(Wt, bt);

    // projections
    dim3 gg(D_/128, M_/128);   // (8, 32)
    sgemm_bias<<<gg, 256>>>(x, Wq, bq, p_q, M_, D_, D_);
    sgemm_bias<<<gg, 256>>>(x, Wk, bk, p_k, M_, D_, D_);
    sgemm_bias<<<gg, 256>>>(x, Wv, bv, p_v, M_, D_, D_);
    sgemm_bias<<<gg, 256>>>(x, Wg, bg, p_g, M_, D_, D_);

    // normalize + head relayout
    norm_split<<<(B_*H_*S_*32)/256, 256>>>();

    // scores, top-k softmax (in-place), attn @ V
    scores_kernel<<<dim3(S_/128, S_/128, BH_), 256>>>();
    topk_softmax<<<B_*H_*S_, 256>>>();
    av_kernel<<<dim3(1, S_/128, BH_), 256>>>();

    // output projection + highway gate
    sgemm_bias<<<gg, 256>>>(p_obsd, Wo, bo, p_out2, M_, D_, D_);
    finalize_kernel<<<(M_*D_/4)/256, 256>>>(x, out);
}

// round 2
// speedup vs baseline: 3.0820x; 3.0820x over previous
#include <cuda_runtime.h>
#include <cuda_fp16.h>
#include <math.h>

#define B_   2
#define S_   2048
#define D_   1024
#define H_   16
#define DH_  64
#define M_   (B_*S_)          // 4096 tokens
#define BH_  (B_*H_)          // 32
#define KK_  512              // top-k
#define MCH_ 16               // mean chunks

#define SA   40               // smem row stride (halves) for 32-col tiles
#define SBP  136              // smem row stride for 128-col B tiles
#define SBV  72               // smem row stride for 64-col V tiles

// ---------------- scratch (static device memory; no allocations) ----------------
__device__ __half g_xh[M_*D_];
__device__ __half g_Wqh[D_*D_];
__device__ __half g_Wkh[D_*D_];
__device__ __half g_Wvh[D_*D_];
__device__ __half g_Wgh[D_*D_];
__device__ __half g_Woh[D_*D_];
__device__ __half g_qh[M_*D_];
__device__ __half g_kh[M_*D_];
__device__ __half g_vh16[M_*D_];
__device__ __half g_gateh[M_*D_];
__device__ __half g_qnh[M_*D_];     // [BH][S][DH]
__device__ __half g_knh[M_*D_];     // [BH][S][DH]
__device__ __half g_vhh[M_*D_];     // [BH][S][DH]
__device__ __half g_obsdh[M_*D_];   // attention output in [B,S,D]
__device__ __half g_out2h[M_*D_];   // after Wo
__device__ float  g_scores[(size_t)BH_*S_*S_];   // 512MB fp32 scores
__device__ __half g_attnh[(size_t)BH_*S_*S_];    // 256MB fp16 attention weights
__device__ float  g_xpart[MCH_*B_*D_];
__device__ float  g_xmean[B_*D_];
__device__ float  g_temp[B_];

// ---------------- mma / ldmatrix helpers ----------------
__device__ __forceinline__ void mma_f16(float* d, const unsigned* a, unsigned b0, unsigned b1){
    asm volatile("mma.sync.aligned.m16n8k16.row.col.f32.f16.f16.f32 "
        "{%0,%1,%2,%3}, {%4,%5,%6,%7}, {%8,%9}, {%0,%1,%2,%3};\n"
        : "+f"(d[0]),"+f"(d[1]),"+f"(d[2]),"+f"(d[3])
        : "r"(a[0]),"r"(a[1]),"r"(a[2]),"r"(a[3]), "r"(b0),"r"(b1));
}
__device__ __forceinline__ void ldsm4(unsigned* r, const __half* p){
    unsigned addr = (unsigned)__cvta_generic_to_shared(p);
    asm volatile("ldmatrix.sync.aligned.m8n8.x4.shared.b16 {%0,%1,%2,%3}, [%4];\n"
        :"=r"(r[0]),"=r"(r[1]),"=r"(r[2]),"=r"(r[3]) : "r"(addr));
}
__device__ __forceinline__ void ldsm4t(unsigned* r, const __half* p){
    unsigned addr = (unsigned)__cvta_generic_to_shared(p);
    asm volatile("ldmatrix.sync.aligned.m8n8.x4.trans.shared.b16 {%0,%1,%2,%3}, [%4];\n"
        :"=r"(r[0]),"=r"(r[1]),"=r"(r[2]),"=r"(r[3]) : "r"(addr));
}

// ---------------- fp32 -> fp16 conversion ----------------
__global__ __launch_bounds__(256) void f2h_kernel(const float* __restrict__ in,
                                                  __half* __restrict__ out){
    int i = blockIdx.x*256 + threadIdx.x;
    float4 v = reinterpret_cast<const float4*>(in)[i];
    reinterpret_cast<__half2*>(out)[2*i]   = __floats2half2_rn(v.x, v.y);
    reinterpret_cast<__half2*>(out)[2*i+1] = __floats2half2_rn(v.z, v.w);
}

// ---------------- mean over sequence (2-stage, deterministic) ----------------
__global__ __launch_bounds__(256) void mean_stage1(const float* __restrict__ x){
    int b  = blockIdx.x / MCH_;
    int ch = blockIdx.x % MCH_;
    int s0 = ch * (S_/MCH_);
    int tid = threadIdx.x;
    float acc[4] = {0.f,0.f,0.f,0.f};
    for (int s = s0; s < s0 + S_/MCH_; ++s){
        const float* xp = x + ((size_t)(b*S_+s))*D_;
        #pragma unroll
        for (int j = 0; j < 4; ++j) acc[j] += xp[tid + j*256];
    }
    #pragma unroll
    for (int j = 0; j < 4; ++j) g_xpart[((size_t)ch*B_ + b)*D_ + tid + j*256] = acc[j];
}

__global__ __launch_bounds__(256) void mean_stage2(){
    int idx = blockIdx.x*256 + threadIdx.x;
    int b = idx / D_, d = idx % D_;
    float s = 0.f;
    #pragma unroll
    for (int ch = 0; ch < MCH_; ++ch) s += g_xpart[((size_t)ch*B_ + b)*D_ + d];
    g_xmean[idx] = s * (1.0f/S_);
}

__global__ __launch_bounds__(256) void temp_kernel(const float* __restrict__ Wt,
                                                   const float* __restrict__ bt){
    __shared__ float red[256];
    int b = blockIdx.x, tid = threadIdx.x;
    float s = 0.f;
    for (int d = tid; d < D_; d += 256) s += g_xmean[b*D_ + d] * Wt[d];
    red[tid] = s; __syncthreads();
    for (int o = 128; o; o >>= 1){ if (tid < o) red[tid] += red[tid+o]; __syncthreads(); }
    if (tid == 0) g_temp[b] = 1.0f/(1.0f + expf(-(red[0] + bt[0]))) + 0.5f;
}

// ---------------- fp16 tensor-core GEMM: C(fp16) = A(fp16) @ W(fp16) + bias(fp32) ----------------
// BM=128, BN=128, BK=32, 256 threads, 8 warps (2M x 4N), warp tile 64x32
__global__ __launch_bounds__(256) void hgemm_bias(const __half* __restrict__ A,
                                                  const __half* __restrict__ Bw,
                                                  const float* __restrict__ bias,
                                                  __half* __restrict__ C,
                                                  int M, int N, int K){
    __shared__ __half As[2][128*SA];
    __shared__ __half Bs[2][32*SBP];
    const int tid = threadIdx.x, lane = tid & 31, wid = tid >> 5;
    const int m0 = blockIdx.y*128, n0 = blockIdx.x*128;
    const int wm = (wid & 1)*64, wn = (wid >> 1)*32;
    const int KT = K >> 5;
    float acc[4][4][4] = {};

    const int ar = tid >> 2, ac = (tid & 3) << 3;   // A: row (+64), col8
    const int br = tid >> 4, bc = (tid & 15) << 3;  // B: row (+16), col8

    // prologue: tile 0
    #pragma unroll
    for (int c = 0; c < 2; ++c){
        *(float4*)&As[0][(ar+c*64)*SA + ac] =
            *(const float4*)(A + (size_t)(m0+ar+c*64)*K + ac);
        *(float4*)&Bs[0][(br+c*16)*SBP + bc] =
            *(const float4*)(Bw + (size_t)(br+c*16)*N + n0 + bc);
    }
    __syncthreads();

    for (int kt = 0; kt < KT; ++kt){
        const int cur = kt & 1;
        float4 ra[2], rb[2];
        const bool nxt = (kt+1 < KT);
        if (nxt){
            int k0 = (kt+1) << 5;
            #pragma unroll
            for (int c = 0; c < 2; ++c){
                ra[c] = *(const float4*)(A + (size_t)(m0+ar+c*64)*K + k0 + ac);
                rb[c] = *(const float4*)(Bw + (size_t)(k0+br+c*16)*N + n0 + bc);
            }
        }
        #pragma unroll
        for (int ks = 0; ks < 2; ++ks){
            unsigned af[4][4], bf[2][4];
            #pragma unroll
            for (int mt = 0; mt < 4; ++mt)
                ldsm4(af[mt], &As[cur][(wm+mt*16+(lane&15))*SA + ks*16 + (lane>>4)*8]);
            #pragma unroll
            for (int g = 0; g < 2; ++g)
                ldsm4t(bf[g], &Bs[cur][(ks*16+(lane&15))*SBP + wn + g*16 + (lane>>4)*8]);
            #pragma unroll
            for (int mt = 0; mt < 4; ++mt)
                #pragma unroll
                for (int g = 0; g < 2; ++g){
                    mma_f16(acc[mt][2*g],   af[mt], bf[g][0], bf[g][1]);
                    mma_f16(acc[mt][2*g+1], af[mt], bf[g][2], bf[g][3]);
                }
        }
        if (nxt){
            #pragma unroll
            for (int c = 0; c < 2; ++c){
                *(float4*)&As[cur^1][(ar+c*64)*SA + ac] = ra[c];
                *(float4*)&Bs[cur^1][(br+c*16)*SBP + bc] = rb[c];
            }
        }
        __syncthreads();
    }

    #pragma unroll
    for (int mt = 0; mt < 4; ++mt){
        int r = m0 + wm + mt*16 + (lane >> 2);
        #pragma unroll
        for (int nt = 0; nt < 4; ++nt){
            int c = n0 + wn + nt*8 + (lane & 3)*2;
            float b0 = bias[c], b1 = bias[c+1];
            *(__half2*)&C[(size_t)r*N + c] =
                __floats2half2_rn(acc[mt][nt][0]+b0, acc[mt][nt][1]+b1);
            *(__half2*)&C[(size_t)(r+8)*N + c] =
                __floats2half2_rn(acc[mt][nt][2]+b0, acc[mt][nt][3]+b1);
        }
    }
}

// ---------------- head split + L2 normalize (q,k) + v relayout (fp16) ----------------
__global__ __launch_bounds__(256) void norm_split(){
    int gw   = (blockIdx.x*256 + threadIdx.x) >> 5;   // one warp per (bh,s)
    int lane = threadIdx.x & 31;
    int s  = gw & (S_-1);
    int bh = gw >> 11;
    int h  = bh & (H_-1), b = bh >> 4;
    size_t src = ((size_t)(b*S_+s))*D_ + h*DH_ + lane*2;
    size_t dst = (size_t)gw * DH_ + lane*2;

    float2 qv = __half22float2(*(const __half2*)(g_qh + src));
    float ss = qv.x*qv.x + qv.y*qv.y;
    #pragma unroll
    for (int o = 16; o; o >>= 1) ss += __shfl_xor_sync(0xFFFFFFFFu, ss, o);
    float inv = 1.0f / fmaxf(sqrtf(ss), 1e-12f);
    *(__half2*)(g_qnh + dst) = __floats2half2_rn(qv.x*inv, qv.y*inv);

    float2 kv = __half22float2(*(const __half2*)(g_kh + src));
    ss = kv.x*kv.x + kv.y*kv.y;
    #pragma unroll
    for (int o = 16; o; o >>= 1) ss += __shfl_xor_sync(0xFFFFFFFFu, ss, o);
    inv = 1.0f / fmaxf(sqrtf(ss), 1e-12f);
    *(__half2*)(g_knh + dst) = __floats2half2_rn(kv.x*inv, kv.y*inv);

    *(__half2*)(g_vhh + dst) = *(const __half2*)(g_vh16 + src);
}

// ---------------- scores[bh] = Qn @ Kn^T / temp[b]  (fp16 mma, fp32 out) ----------------
// BM=BN=128, BK=32, K=64. B fragments loaded non-trans from kn's [n][k] layout.
__global__ __launch_bounds__(256) void scores_mma(){
    const int bh = blockIdx.z, b = bh >> 4;
    const __half* Q  = g_qnh + (size_t)bh*S_*DH_;
    const __half* Kn = g_knh + (size_t)bh*S_*DH_;
    __shared__ __half As[2][128*SA];
    __shared__ __half Bs[2][128*SA];
    const int tid = threadIdx.x, lane = tid & 31, wid = tid >> 5;
    const int m0 = blockIdx.y*128, n0 = blockIdx.x*128;
    const int wm = (wid & 1)*64, wn = (wid >> 1)*32;
    float acc[4][4][4] = {};

    const int ar = tid >> 2, ac = (tid & 3) << 3;

    #pragma unroll
    for (int c = 0; c < 2; ++c){
        *(float4*)&As[0][(ar+c*64)*SA + ac] =
            *(const float4*)(Q + (size_t)(m0+ar+c*64)*DH_ + ac);
        *(float4*)&Bs[0][(ar+c*64)*SA + ac] =
            *(const float4*)(Kn + (size_t)(n0+ar+c*64)*DH_ + ac);
    }
    __syncthreads();

    const int KT = DH_ >> 5;  // 2
    for (int kt = 0; kt < KT; ++kt){
        const int cur = kt & 1;
        float4 ra[2], rb[2];
        const bool nxt = (kt+1 < KT);
        if (nxt){
            int k0 = (kt+1) << 5;
            #pragma unroll
            for (int c = 0; c < 2; ++c){
                ra[c] = *(const float4*)(Q  + (size_t)(m0+ar+c*64)*DH_ + k0 + ac);
                rb[c] = *(const float4*)(Kn + (size_t)(n0+ar+c*64)*DH_ + k0 + ac);
            }
        }
        #pragma unroll
        for (int ks = 0; ks < 2; ++ks){
            unsigned af[4][4], bf[2][4];
            #pragma unroll
            for (int mt = 0; mt < 4; ++mt)
                ldsm4(af[mt], &As[cur][(wm+mt*16+(lane&15))*SA + ks*16 + (lane>>4)*8]);
            #pragma unroll
            for (int g = 0; g < 2; ++g)
                ldsm4(bf[g], &Bs[cur][(wn + g*16 + ((lane>>4)<<3) + (lane&7))*SA
                                      + ks*16 + ((lane>>3)&1)*8]);
            #pragma unroll
            for (int mt = 0; mt < 4; ++mt)
                #pragma unroll
                for (int g = 0; g < 2; ++g){
                    mma_f16(acc[mt][2*g],   af[mt], bf[g][0], bf[g][1]);
                    mma_f16(acc[mt][2*g+1], af[mt], bf[g][2], bf[g][3]);
                }
        }
        if (nxt){
            #pragma unroll
            for (int c = 0; c < 2; ++c){
                *(float4*)&As[cur^1][(ar+c*64)*SA + ac] = ra[c];
                *(float4*)&Bs[cur^1][(ar+c*64)*SA + ac] = rb[c];
            }
        }
        __syncthreads();
    }

    const float sc = 1.0f / g_temp[b];
    #pragma unroll
    for (int mt = 0; mt < 4; ++mt){
        int r = m0 + wm + mt*16 + (lane >> 2);
        #pragma unroll
        for (int nt = 0; nt < 4; ++nt){
            int c = n0 + wn + nt*8 + (lane & 3)*2;
            float2 o0 = make_float2(acc[mt][nt][0]*sc, acc[mt][nt][1]*sc);
            float2 o1 = make_float2(acc[mt][nt][2]*sc, acc[mt][nt][3]*sc);
            *(float2*)&g_scores[((size_t)bh*S_ + r)*S_ + c]     = o0;
            *(float2*)&g_scores[((size_t)bh*S_ + r + 8)*S_ + c] = o1;
        }
    }
}

// ---------------- exact top-512 radix-select + softmax -> fp16 weights ----------------
__global__ __launch_bounds__(256) void topk_softmax(){
    const size_t row = blockIdx.x;
    const float* sp = g_scores + row*(size_t)S_;
    __half* ap = g_attnh + row*(size_t)S_;
    __shared__ unsigned hist[256];
    __shared__ unsigned sufs[256];
    __shared__ unsigned wsum[8];
    __shared__ float fr[8];
    __shared__ unsigned s_bin, s_above;
    __shared__ float s_mx, s_sum;
    const int tid = threadIdx.x, lane = tid & 31, wid = tid >> 5;

    float v[8]; unsigned key[8];
    #pragma unroll
    for (int i = 0; i < 8; ++i){
        v[i] = sp[i*256 + tid];
        unsigned u = __float_as_uint(v[i]);
        key[i] = u ^ (((unsigned)((int)u >> 31)) | 0x80000000u);
    }

    unsigned prefix = 0, remaining = KK_;
    #pragma unroll
    for (int shift = 24; shift >= 0; shift -= 8){
        hist[tid] = 0; __syncthreads();
        unsigned pmask = (shift == 24) ? 0u : (0xFFFFFFFFu << (shift+8));
        #pragma unroll
        for (int i = 0; i < 8; ++i)
            if ((key[i] & pmask) == prefix) atomicAdd(&hist[(key[i] >> shift) & 255], 1u);
        __syncthreads();
        // suffix sum over bins (bin b handled by thread 255-b)
        unsigned x = hist[255 - tid];
        #pragma unroll
        for (int o = 1; o < 32; o <<= 1){
            unsigned t = __shfl_up_sync(0xFFFFFFFFu, x, o);
            if (lane >= o) x += t;
        }
        if (lane == 31) wsum[wid] = x;
        __syncthreads();
        if (tid < 8){
            unsigned w = wsum[tid];
            #pragma unroll
            for (int o = 1; o < 8; o <<= 1){
                unsigned t = __shfl_up_sync(0xFFu, w, o);
                if (tid >= o) w += t;
            }
            wsum[tid] = w;
        }
        __syncthreads();
        unsigned suf = x + (wid ? wsum[wid-1] : 0u);
        sufs[255 - tid] = suf;
        __syncthreads();
        unsigned Sb  = sufs[tid];
        unsigned Sb1 = (tid < 255) ? sufs[tid+1] : 0u;
        if (Sb >= remaining && Sb1 < remaining){ s_bin = (unsigned)tid; s_above = Sb1; }
        __syncthreads();
        remaining -= s_above;
        prefix |= (s_bin << shift);
    }
    const unsigned T = prefix;

    float mx = -3.402823466e38f;
    #pragma unroll
    for (int i = 0; i < 8; ++i) mx = fmaxf(mx, v[i]);
    #pragma unroll
    for (int o = 16; o; o >>= 1) mx = fmaxf(mx, __shfl_xor_sync(0xFFFFFFFFu, mx, o));
    if (lane == 0) fr[wid] = mx;
    __syncthreads();
    if (tid == 0){
        float m = fr[0];
        #pragma unroll
        for (int j = 1; j < 8; ++j) m = fmaxf(m, fr[j]);
        s_mx = m;
    }
    __syncthreads();
    mx = s_mx;

    float e[8]; float ls = 0.f;
    #pragma unroll
    for (int i = 0; i < 8; ++i){
        e[i] = (key[i] >= T) ? expf(v[i] - mx) : 0.0f;
        ls += e[i];
    }
    #pragma unroll
    for (int o = 16; o; o >>= 1) ls += __shfl_xor_sync(0xFFFFFFFFu, ls, o);
    if (lane == 0) fr[wid] = ls;
    __syncthreads();
    if (tid == 0){
        float m = 0.f;
        #pragma unroll
        for (int j = 0; j < 8; ++j) m += fr[j];
        s_sum = m;
    }
    __syncthreads();
    const float inv = 1.0f / s_sum;
    #pragma unroll
    for (int i = 0; i < 8; ++i) ap[i*256 + tid] = __float2half(e[i]*inv);
}

// ---------------- O = attn @ V  (fp16 mma) ----------------
// BM=128, BN=64, BK=32, 8 warps (4M x 2N), warp tile 32x32, K=2048
__global__ __launch_bounds__(256) void av_mma(){
    const int bh = blockIdx.z;
    const int m0 = blockIdx.y*128;
    const __half* A = g_attnh + (size_t)bh*S_*S_;
    const __half* V = g_vhh   + (size_t)bh*S_*DH_;
    __shared__ __half As[2][128*SA];
    __shared__ __half Bs[2][32*SBV];
    const int tid = threadIdx.x, lane = tid & 31, wid = tid >> 5;
    const int wm = (wid & 3)*32, wn = (wid >> 2)*32;
    float acc[2][4][4] = {};

    const int ar = tid >> 2, ac = (tid & 3) << 3;   // A rows (+64)
    const int br = tid >> 3, bc = (tid & 7) << 3;   // B: 32 rows x 8 groups

    #pragma unroll
    for (int c = 0; c < 2; ++c)
        *(float4*)&As[0][(ar+c*64)*SA + ac] =
            *(const float4*)(A + (size_t)(m0+ar+c*64)*S_ + ac);
    *(float4*)&Bs[0][br*SBV + bc] = *(const float4*)(V + (size_t)br*DH_ + bc);
    __syncthreads();

    const int KT = S_ >> 5;  // 64
    for (int kt = 0; kt < KT; ++kt){
        const int cur = kt & 1;
        float4 ra[2], rb;
        const bool nxt = (kt+1 < KT);
        if (nxt){
            int k0 = (kt+1) << 5;
            #pragma unroll
            for (int c = 0; c < 2; ++c)
                ra[c] = *(const float4*)(A + (size_t)(m0+ar+c*64)*S_ + k0 + ac);
            rb = *(const float4*)(V + (size_t)(k0+br)*DH_ + bc);
        }
        #pragma unroll
        for (int ks = 0; ks < 2; ++ks){
            unsigned af[2][4], bf[2][4];
            #pragma unroll
            for (int mt = 0; mt < 2; ++mt)
                ldsm4(af[mt], &As[cur][(wm+mt*16+(lane&15))*SA + ks*16 + (lane>>4)*8]);
            #pragma unroll
            for (int g = 0; g < 2; ++g)
                ldsm4t(bf[g], &Bs[cur][(ks*16+(lane&15))*SBV + wn + g*16 + (lane>>4)*8]);
            #pragma unroll
            for (int mt = 0; mt < 2; ++mt)
                #pragma unroll
                for (int g = 0; g < 2; ++g){
                    mma_f16(acc[mt][2*g],   af[mt], bf[g][0], bf[g][1]);
                    mma_f16(acc[mt][2*g+1], af[mt], bf[g][2], bf[g][3]);
                }
        }
        if (nxt){
            #pragma unroll
            for (int c = 0; c < 2; ++c)
                *(float4*)&As[cur^1][(ar+c*64)*SA + ac] = ra[c];
            *(float4*)&Bs[cur^1][br*SBV + bc] = rb;
        }
        __syncthreads();
    }

    const int bb = bh >> 4, h = bh & (H_-1);
    #pragma unroll
    for (int mt = 0; mt < 2; ++mt){
        int s_idx = m0 + wm + mt*16 + (lane >> 2);
        size_t grow0 = (size_t)(bb*S_ + s_idx)*D_;
        size_t grow1 = (size_t)(bb*S_ + s_idx + 8)*D_;
        #pragma unroll
        for (int nt = 0; nt < 4; ++nt){
            int c = h*DH_ + wn + nt*8 + (lane & 3)*2;
            *(__half2*)&g_obsdh[grow0 + c] = __floats2half2_rn(acc[mt][nt][0], acc[mt][nt][1]);
            *(__half2*)&g_obsdh[grow1 + c] = __floats2half2_rn(acc[mt][nt][2], acc[mt][nt][3]);
        }
    }
}

// ---------------- highway gating ----------------
__global__ __launch_bounds__(256) void finalize_kernel(const float* __restrict__ x,
                                                       float* __restrict__ out){
    int i = blockIdx.x*256 + threadIdx.x;    // over M*D/2 pairs
    float2 xv = reinterpret_cast<const float2*>(x)[i];
    float2 gv = __half22float2(reinterpret_cast<const __half2*>(g_gateh)[i]);
    float2 ov = __half22float2(reinterpret_cast<const __half2*>(g_out2h)[i]);
    float2 r;
    float g;
    g = 1.0f/(1.0f+expf(-gv.x)); r.x = g*ov.x + (1.0f-g)*xv.x;
    g = 1.0f/(1.0f+expf(-gv.y)); r.y = g*ov.y + (1.0f-g)*xv.y;
    reinterpret_cast<float2*>(out)[i] = r;
}

// ---------------- launch ----------------
extern "C" void kernel_launch(void* const* d_in, const int* in_sizes, int n_in,
                              void* d_out, int out_size){
    (void)in_sizes; (void)n_in; (void)out_size;
    const float* x  = (const float*)d_in[0];
    const float* Wq = (const float*)d_in[1];  const float* bq = (const float*)d_in[2];
    const float* Wk = (const float*)d_in[3];  const float* bk = (const float*)d_in[4];
    const float* Wv = (const float*)d_in[5];  const float* bv = (const float*)d_in[6];
    const float* Wo = (const float*)d_in[7];  const float* bo = (const float*)d_in[8];
    const float* Wt = (const float*)d_in[9];  const float* bt = (const float*)d_in[10];
    const float* Wg = (const float*)d_in[11]; const float* bg = (const float*)d_in[12];
    float* out = (float*)d_out;

    __half *xh,*Wqh,*Wkh,*Wvh,*Wgh,*Woh,*qh,*kh,*vh,*gh,*obsdh,*out2h;
    cudaGetSymbolAddress((void**)&xh,    g_xh);
    cudaGetSymbolAddress((void**)&Wqh,   g_Wqh);
    cudaGetSymbolAddress((void**)&Wkh,   g_Wkh);
    cudaGetSymbolAddress((void**)&Wvh,   g_Wvh);
    cudaGetSymbolAddress((void**)&Wgh,   g_Wgh);
    cudaGetSymbolAddress((void**)&Woh,   g_Woh);
    cudaGetSymbolAddress((void**)&qh,    g_qh);
    cudaGetSymbolAddress((void**)&kh,    g_kh);
    cudaGetSymbolAddress((void**)&vh,    g_vh16);
    cudaGetSymbolAddress((void**)&gh,    g_gateh);
    cudaGetSymbolAddress((void**)&obsdh, g_obsdh);
    cudaGetSymbolAddress((void**)&out2h, g_out2h);

    // conversions
    f2h_kernel<<<(M_*D_)/1024, 256>>>(x,  xh);
    f2h_kernel<<<(D_*D_)/1024, 256>>>(Wq, Wqh);
    f2h_kernel<<<(D_*D_)/1024, 256>>>(Wk, Wkh);
    f2h_kernel<<<(D_*D_)/1024, 256>>>(Wv, Wvh);
    f2h_kernel<<<(D_*D_)/1024, 256>>>(Wg, Wgh);
    f2h_kernel<<<(D_*D_)/1024, 256>>>(Wo, Woh);

    // temperature path (fp32)
    mean_stage1<<<B_*MCH_, 256>>>(x);
    mean_stage2<<<(B_*D_)/256, 256>>>();
    temp_kernel<<<B_, 256>>>(Wt, bt);

    // projections (tensor core)
    dim3 gg(D_/128, M_/128);   // (8, 32)
    hgemm_bias<<<gg, 256>>>(xh, Wqh, bq, qh, M_, D_, D_);
    hgemm_bias<<<gg, 256>>>(xh, Wkh, bk, kh, M_, D_, D_);
    hgemm_bias<<<gg, 256>>>(xh, Wvh, bv, vh, M_, D_, D_);
    hgemm_bias<<<gg, 256>>>(xh, Wgh, bg, gh, M_, D_, D_);

    // normalize + head relayout
    norm_split<<<(BH_*S_*32)/256, 256>>>();

    // scores, top-k softmax, attn @ V
    scores_mma<<<dim3(S_/128, S_/128, BH_), 256>>>();
    topk_softmax<<<BH_*S_, 256>>>();
    av_mma<<<dim3(1, S_/128, BH_), 256>>>();

    // output projection + highway gate
    hgemm_bias<<<gg, 256>>>(obsdh, Woh, bo, out2h, M_, D_, D_);
    finalize_kernel<<<(M_*D_/2)/256, 256>>>(x, out);
}